// round 7
// baseline (speedup 1.0000x reference)
#include <cuda_runtime.h>
#include <cuda_bf16.h>

// Shapes
#define BB   4
#define CC   64
#define DCC  16
#define FF   256
#define TT   384
#define NN   (FF*TT)          // 98304
#define PP   (BB*NN)          // 393216

typedef unsigned long long u64;

// 0.25 (1/sqrt(DC)) * log2(e): dot computed in log2 domain
#define QSCALE 0.36067376022224085f

// ---------------------------------------------------------------------------
// Scratch (device globals; allocation is forbidden)
// ---------------------------------------------------------------------------
__device__ float g_fqkv   [(size_t)BB*48*NN];  // [b][c48][f][t]   natural
__device__ float g_fqkv_t [(size_t)BB*48*NN];  // [b][t][c48][f]   transposed
__device__ float g_tqk    [(size_t)BB*32*NN];  // [b][c32][f][t]   natural
__device__ float g_fout_t [(size_t)BB*16*NN];  // [b][t][c16][f]
__device__ float g_fout   [(size_t)BB*16*NN];  // [b][c16][f][t]
__device__ float g_tout   [(size_t)BB*16*NN];  // [b][c16][f][t]

// ---------------------------------------------------------------------------
// Packed f32x2 helpers
// ---------------------------------------------------------------------------
__device__ __forceinline__ u64 fma2(u64 a, u64 b, u64 c) {
    u64 d;
    asm("fma.rn.f32x2 %0, %1, %2, %3;" : "=l"(d) : "l"(a), "l"(b), "l"(c));
    return d;
}
__device__ __forceinline__ u64 add2(u64 a, u64 b) {
    u64 d;
    asm("add.rn.f32x2 %0, %1, %2;" : "=l"(d) : "l"(a), "l"(b));
    return d;
}
__device__ __forceinline__ u64 sub2(u64 a, u64 b) {
    u64 d;
    asm("sub.rn.f32x2 %0, %1, %2;" : "=l"(d) : "l"(a), "l"(b));
    return d;
}
__device__ __forceinline__ u64 mul2(u64 a, u64 b) {
    u64 d;
    asm("mul.rn.f32x2 %0, %1, %2;" : "=l"(d) : "l"(a), "l"(b));
    return d;
}
__device__ __forceinline__ u64 pack2(float lo, float hi) {
    u64 d;
    asm("mov.b64 %0, {%1, %2};" : "=l"(d) : "f"(lo), "f"(hi));
    return d;
}
__device__ __forceinline__ void unpack2(u64 a, float& lo, float& hi) {
    asm("mov.b64 {%0, %1}, %2;" : "=f"(lo), "=f"(hi) : "l"(a));
}
__device__ __forceinline__ float hsum2(u64 a) {
    float lo, hi; unpack2(a, lo, hi); return lo + hi;
}
__device__ __forceinline__ u64 bcast(float x) { return pack2(x, x); }

// Packed-exp constants — 6 u64 (12 regs)
struct EC { u64 M, A4, A3, A2, A1, ONE; };
__device__ __forceinline__ EC make_ec() {
    EC e;
    e.M   = bcast(12582912.0f);        // 2^23 + 2^22
    e.A4  = bcast(9.6181291076e-3f);   // ln2^4/24
    e.A3  = bcast(5.5504108664e-2f);   // ln2^3/6
    e.A2  = bcast(2.4022650696e-1f);   // ln2^2/2
    e.A1  = bcast(6.9314718056e-1f);   // ln2
    e.ONE = bcast(1.0f);
    return e;
}

// Packed 2^t on both lanes, degree-4 (max rel err ~4e-5).
__device__ __forceinline__ u64 pexp2(u64 t2, const EC& e) {
    u64 z2  = add2(t2, e.M);              // round-to-nearest int in mantissa
    u64 fi2 = sub2(z2, e.M);              // exact
    u64 u2  = sub2(t2, fi2);              // |u| <= 0.5
    u64 p   = fma2(u2, e.A4, e.A3);
    p = fma2(u2, p, e.A2);
    p = fma2(u2, p, e.A1);
    p = fma2(u2, p, e.ONE);               // 2^u
    unsigned lo, hi;
    asm("mov.b64 {%0, %1}, %2;" : "=r"(lo), "=r"(hi) : "l"(z2));
    unsigned s0 = (lo + 0xB4C0007Fu) << 23;   // (bits - 0x4B400000 + 127) << 23
    unsigned s1 = (hi + 0xB4C0007Fu) << 23;
    u64 sc;
    asm("mov.b64 %0, {%1, %2};" : "=l"(sc) : "r"(s0), "r"(s1));
    return mul2(p, sc);                   // 2^round(t) * 2^u
}

// Pair-dot: 16 channels of q (broadcast-packed) against a pair-interleaved
// K row; result lanes = the two scores. No horizontal sum needed.
__device__ __forceinline__ u64 dotp(const u64 (&qb)[16], const u64* krow) {
    const ulonglong2* kp = (const ulonglong2*)krow;
    ulonglong2 m0=kp[0], m1=kp[1], m2=kp[2], m3=kp[3];
    u64 a0 = fma2(qb[0],  m0.x, 0), a1 = fma2(qb[1],  m0.y, 0);
    a0 = fma2(qb[2],  m1.x, a0);  a1 = fma2(qb[3],  m1.y, a1);
    a0 = fma2(qb[4],  m2.x, a0);  a1 = fma2(qb[5],  m2.y, a1);
    a0 = fma2(qb[6],  m3.x, a0);  a1 = fma2(qb[7],  m3.y, a1);
    ulonglong2 m4=kp[4], m5=kp[5], m6=kp[6], m7=kp[7];
    a0 = fma2(qb[8],  m4.x, a0);  a1 = fma2(qb[9],  m4.y, a1);
    a0 = fma2(qb[10], m5.x, a0);  a1 = fma2(qb[11], m5.y, a1);
    a0 = fma2(qb[12], m6.x, a0);  a1 = fma2(qb[13], m6.y, a1);
    a0 = fma2(qb[14], m7.x, a0);  a1 = fma2(qb[15], m7.y, a1);
    return add2(a0, a1);
}

// ---------------------------------------------------------------------------
// Dummy kernel: shifts the ncu profiled launch slot onto k_fattn.
// ---------------------------------------------------------------------------
__global__ void k_dummy() {}

// ---------------------------------------------------------------------------
// Kernel 1: fused fqkv (48ch) + tqk (32ch) conv1x1 + BN + PReLU (packed FMA)
// ---------------------------------------------------------------------------
__global__ __launch_bounds__(256) void k_qkv(
    const float* __restrict__ x,
    const float* __restrict__ fw, const float* __restrict__ fg,
    const float* __restrict__ fb, const float* __restrict__ fm,
    const float* __restrict__ fv, const float* __restrict__ fa,
    const float* __restrict__ tw, const float* __restrict__ tg,
    const float* __restrict__ tb, const float* __restrict__ tm,
    const float* __restrict__ tvv, const float* __restrict__ ta)
{
    __shared__ float ws[80*64];
    __shared__ float sa[80], sbb[80], sal[80];
    int tid = threadIdx.x;
    for (int i = tid; i < 48*64; i += 256) ws[i] = fw[i];
    for (int i = tid; i < 32*64; i += 256) ws[48*64 + i] = tw[i];
    if (tid < 80) {
        float g, be, mn, vr, al;
        if (tid < 48) { g=fg[tid]; be=fb[tid]; mn=fm[tid]; vr=fv[tid]; al=fa[tid]; }
        else { int o=tid-48; g=tg[o]; be=tb[o]; mn=tm[o]; vr=tvv[o]; al=ta[o]; }
        float a = g * rsqrtf(vr + 1e-5f);
        sa[tid] = a; sbb[tid] = be - mn*a; sal[tid] = al;
    }
    __syncthreads();

    size_t p   = (size_t)blockIdx.x*256 + tid;
    int    b   = (int)(p / NN);
    int    rem = (int)(p % NN);

    u64 xv[32];
    const float* xb = x + (size_t)b*CC*NN + rem;
    #pragma unroll
    for (int c = 0; c < 32; c++)
        xv[c] = pack2(xb[(size_t)(2*c)*NN], xb[(size_t)(2*c+1)*NN]);

    for (int o = 0; o < 80; o++) {
        const ulonglong2* wp = (const ulonglong2*)(ws + o*64);
        u64 a0 = 0, a1 = 0;
        #pragma unroll
        for (int i = 0; i < 16; i++) {
            ulonglong2 w = wp[i];
            a0 = fma2(xv[2*i],   w.x, a0);
            a1 = fma2(xv[2*i+1], w.y, a1);
        }
        float acc = hsum2(add2(a0, a1));
        float yn = acc*sa[o] + sbb[o];
        float r  = yn >= 0.f ? yn : sal[o]*yn;
        if (o < 48) g_fqkv[((size_t)b*48 + o     )*NN + rem] = r;
        else        g_tqk [((size_t)b*32 + (o-48))*NN + rem] = r;
    }
}

// ---------------------------------------------------------------------------
// Transposes (32x32 smem tiles, coalesced both ways)
// ---------------------------------------------------------------------------
__global__ void k_trans_qkv() {  // [b][cf=12288][t=384] -> [b][t][cf]
    __shared__ float tile[32][33];
    int b = blockIdx.z;
    size_t base = (size_t)b * 12288 * 384;
    int r0 = blockIdx.y*32, q0 = blockIdx.x*32;
    for (int i = threadIdx.y; i < 32; i += 8)
        tile[i][threadIdx.x] = g_fqkv[base + (size_t)(r0+i)*384 + q0 + threadIdx.x];
    __syncthreads();
    for (int i = threadIdx.y; i < 32; i += 8)
        g_fqkv_t[base + (size_t)(q0+i)*12288 + r0 + threadIdx.x] = tile[threadIdx.x][i];
}

__global__ void k_trans_fout() { // [b][t=384][cf=4096] -> [b][cf][t]
    __shared__ float tile[32][33];
    int b = blockIdx.z;
    size_t base = (size_t)b * 4096 * 384;
    int r0 = blockIdx.y*32, q0 = blockIdx.x*32;   // r over t, q over cf
    for (int i = threadIdx.y; i < 32; i += 8)
        tile[i][threadIdx.x] = g_fout_t[base + (size_t)(r0+i)*4096 + q0 + threadIdx.x];
    __syncthreads();
    for (int i = threadIdx.y; i < 32; i += 8)
        g_fout[base + (size_t)(q0+i)*384 + r0 + threadIdx.x] = tile[threadIdx.x][i];
}

// ---------------------------------------------------------------------------
// Kernel 3: frequency attention. Block = (t, b); thread = f row.
// K AND V pair-interleaved: pr2 multiplies V directly (no unpack/repack);
// per-channel accumulators carry (even-y, odd-y) partial sums, folded by
// one hsum2 per channel at the end.
// ---------------------------------------------------------------------------
__global__ __launch_bounds__(256) void k_fattn() {
    __shared__ __align__(16) u64 ks2[128*18];   // (K[2y2][c], K[2y2+1][c])
    __shared__ __align__(16) u64 vs2[128*18];   // (V[2y2][c], V[2y2+1][c])
    int t = blockIdx.x, b = blockIdx.y;
    int tid = threadIdx.x;
    const float* base = g_fqkv_t + (size_t)(b*TT + t) * (48*FF);

    for (int i = tid; i < 2048; i += 256) {
        int y2 = i & 127, c = i >> 7;
        float2 kv = *(const float2*)(base + (16+c)*FF + 2*y2);
        ks2[y2*18 + c] = pack2(kv.x, kv.y);
        float2 vv = *(const float2*)(base + (32+c)*FF + 2*y2);
        vs2[y2*18 + c] = pack2(vv.x, vv.y);
    }
    u64 qb[16];
    #pragma unroll
    for (int c = 0; c < 16; c++) {
        float v = base[c*FF + tid] * QSCALE;
        qb[c] = pack2(v, v);
    }
    __syncthreads();

    const EC ec = make_ec();
    u64 sum2 = 0;
    u64 acc[16];
    #pragma unroll
    for (int c = 0; c < 16; c++) acc[c] = 0;

    for (int y2 = 0; y2 < 128; y2++) {
        u64 t2  = dotp(qb, ks2 + y2*18);
        u64 pr2 = pexp2(t2, ec);
        sum2 = add2(sum2, pr2);
        const ulonglong2* vp = (const ulonglong2*)(vs2 + y2*18);
        ulonglong2 m0=vp[0], m1=vp[1], m2=vp[2], m3=vp[3];
        acc[0] = fma2(pr2, m0.x, acc[0]);  acc[1] = fma2(pr2, m0.y, acc[1]);
        acc[2] = fma2(pr2, m1.x, acc[2]);  acc[3] = fma2(pr2, m1.y, acc[3]);
        acc[4] = fma2(pr2, m2.x, acc[4]);  acc[5] = fma2(pr2, m2.y, acc[5]);
        acc[6] = fma2(pr2, m3.x, acc[6]);  acc[7] = fma2(pr2, m3.y, acc[7]);
        ulonglong2 m4=vp[4], m5=vp[5], m6=vp[6], m7=vp[7];
        acc[8]  = fma2(pr2, m4.x, acc[8]);   acc[9]  = fma2(pr2, m4.y, acc[9]);
        acc[10] = fma2(pr2, m5.x, acc[10]);  acc[11] = fma2(pr2, m5.y, acc[11]);
        acc[12] = fma2(pr2, m6.x, acc[12]);  acc[13] = fma2(pr2, m6.y, acc[13]);
        acc[14] = fma2(pr2, m7.x, acc[14]);  acc[15] = fma2(pr2, m7.y, acc[15]);
    }
    float inv = 1.0f / hsum2(sum2);
    float* op = g_fout_t + (size_t)(b*TT + t) * (16*FF);
    #pragma unroll
    for (int c = 0; c < 16; c++)
        op[c*FF + tid] = hsum2(acc[c]) * inv;
}

// ---------------------------------------------------------------------------
// Kernel 5: time attention (causal). Block = (f, b); thread = t row.
// Pair-interleaved K; masked single-lane tail for even t. Dynamic smem (51KB).
// ---------------------------------------------------------------------------
__global__ __launch_bounds__(384, 2) void k_tattn() {
    extern __shared__ __align__(16) char tsm[];
    u64*   ks2 = (u64*)tsm;                        // 192*18*8 = 27648 B
    float* vs  = (float*)(tsm + 192*18*8);         // 384*16*4 = 24576 B
    int f = blockIdx.x, b = blockIdx.y;
    int tid = threadIdx.x;  // t

    const float* ktb = g_tqk  + (((size_t)b*32 + 16)*FF + f)*TT;
    const float* vb  = g_fout + (((size_t)b*16     )*FF + f)*TT;
    for (int i = tid; i < 3072; i += 384) {
        int y2 = i % 192, c = i / 192;
        float2 kv = *(const float2*)(ktb + (size_t)c*NN + 2*y2);
        ks2[y2*18 + c] = pack2(kv.x, kv.y);
    }
    for (int i = tid; i < 6144; i += 384) {
        int c = i / 384, y = i % 384;
        vs[y*16 + c] = vb[(size_t)c*NN + y];
    }
    u64 qb[16];
    const float* qsrc = g_tqk + (((size_t)b*32)*FF + f)*TT;
    #pragma unroll
    for (int c = 0; c < 16; c++) {
        float v = qsrc[(size_t)c*NN + tid] * QSCALE;
        qb[c] = pack2(v, v);
    }
    __syncthreads();

    const EC ec = make_ec();
    int t = tid;
    u64 sum2 = 0;
    u64 acc[8];
    #pragma unroll
    for (int c = 0; c < 8; c++) acc[c] = 0;

    int np = (t + 1) >> 1;              // full pairs cover y = 0 .. 2*np-1 <= t
    for (int y2 = 0; y2 < np; y2++) {
        u64 t2  = dotp(qb, ks2 + y2*18);
        u64 pr2 = pexp2(t2, ec);
        sum2 = add2(sum2, pr2);
        float p0, p1; unpack2(pr2, p0, p1);
        u64 pa = pack2(p0, p0), pb = pack2(p1, p1);
        const ulonglong2* v0 = (const ulonglong2*)(vs + (2*y2)*16);
        ulonglong2 w0=v0[0], w1=v0[1], w2=v0[2], w3=v0[3];
        acc[0]=fma2(pa,w0.x,acc[0]);  acc[1]=fma2(pa,w0.y,acc[1]);
        acc[2]=fma2(pa,w1.x,acc[2]);  acc[3]=fma2(pa,w1.y,acc[3]);
        acc[4]=fma2(pa,w2.x,acc[4]);  acc[5]=fma2(pa,w2.y,acc[5]);
        acc[6]=fma2(pa,w3.x,acc[6]);  acc[7]=fma2(pa,w3.y,acc[7]);
        const ulonglong2* v1 = (const ulonglong2*)(vs + (2*y2+1)*16);
        ulonglong2 x0=v1[0], x1=v1[1], x2=v1[2], x3=v1[3];
        acc[0]=fma2(pb,x0.x,acc[0]);  acc[1]=fma2(pb,x0.y,acc[1]);
        acc[2]=fma2(pb,x1.x,acc[2]);  acc[3]=fma2(pb,x1.y,acc[3]);
        acc[4]=fma2(pb,x2.x,acc[4]);  acc[5]=fma2(pb,x2.y,acc[5]);
        acc[6]=fma2(pb,x3.x,acc[6]);  acc[7]=fma2(pb,x3.y,acc[7]);
    }
    if (!(t & 1)) {                     // tail: y = t, lane0 of pair t/2
        u64 t2  = dotp(qb, ks2 + (t >> 1)*18);
        u64 pr2 = pexp2(t2, ec);
        float p0, p1; unpack2(pr2, p0, p1);
        sum2 = add2(sum2, pack2(p0, 0.f));
        u64 pa = pack2(p0, p0);
        const ulonglong2* v0 = (const ulonglong2*)(vs + t*16);
        ulonglong2 w0=v0[0], w1=v0[1], w2=v0[2], w3=v0[3];
        acc[0]=fma2(pa,w0.x,acc[0]);  acc[1]=fma2(pa,w0.y,acc[1]);
        acc[2]=fma2(pa,w1.x,acc[2]);  acc[3]=fma2(pa,w1.y,acc[3]);
        acc[4]=fma2(pa,w2.x,acc[4]);  acc[5]=fma2(pa,w2.y,acc[5]);
        acc[6]=fma2(pa,w3.x,acc[6]);  acc[7]=fma2(pa,w3.y,acc[7]);
    }
    float inv = 1.0f / hsum2(sum2);
    float* op = g_tout + (((size_t)b*16)*FF + f)*TT + t;
    #pragma unroll
    for (int c = 0; c < 8; c++) {
        float lo, hi; unpack2(acc[c], lo, hi);
        op[(size_t)(2*c)*NN]   = lo * inv;
        op[(size_t)(2*c+1)*NN] = hi * inv;
    }
}

// ---------------------------------------------------------------------------
// Kernel 6: proj conv1x1 (64<-16) + BN + PReLU + residual (packed FMA)
// ---------------------------------------------------------------------------
__global__ __launch_bounds__(256) void k_proj(
    const float* __restrict__ x,
    const float* __restrict__ pw, const float* __restrict__ pg,
    const float* __restrict__ pb, const float* __restrict__ pm,
    const float* __restrict__ pv, const float* __restrict__ pa,
    float* __restrict__ out)
{
    __shared__ float ws[64*16];
    __shared__ float sa[64], sbb[64], sal[64];
    int tid = threadIdx.x;
    for (int i = tid; i < 1024; i += 256) ws[i] = pw[i];
    if (tid < 64) {
        float a = pg[tid] * rsqrtf(pv[tid] + 1e-5f);
        sa[tid] = a; sbb[tid] = pb[tid] - pm[tid]*a; sal[tid] = pa[tid];
    }
    __syncthreads();

    size_t p   = (size_t)blockIdx.x*256 + tid;
    int    b   = (int)(p / NN);
    int    rem = (int)(p % NN);

    u64 tv[8];
    #pragma unroll
    for (int c = 0; c < 8; c++)
        tv[c] = pack2(g_tout[((size_t)b*16 + 2*c  )*NN + rem],
                      g_tout[((size_t)b*16 + 2*c+1)*NN + rem]);

    const float* xb = x   + (size_t)b*CC*NN + rem;
    float*       ob = out + (size_t)b*CC*NN + rem;
    for (int o = 0; o < 64; o++) {
        const ulonglong2* wp = (const ulonglong2*)(ws + o*16);
        ulonglong2 w0 = wp[0], w1 = wp[1], w2 = wp[2], w3 = wp[3];
        u64 a0 = fma2(tv[0], w0.x, 0), a1 = fma2(tv[1], w0.y, 0);
        a0 = fma2(tv[2], w1.x, a0);  a1 = fma2(tv[3], w1.y, a1);
        a0 = fma2(tv[4], w2.x, a0);  a1 = fma2(tv[5], w2.y, a1);
        a0 = fma2(tv[6], w3.x, a0);  a1 = fma2(tv[7], w3.y, a1);
        float acc = hsum2(add2(a0, a1));
        float yn = acc*sa[o] + sbb[o];
        float r  = yn >= 0.f ? yn : sal[o]*yn;
        ob[(size_t)o*NN] = r + xb[(size_t)o*NN];
    }
}

// ---------------------------------------------------------------------------
extern "C" void kernel_launch(void* const* d_in, const int* in_sizes, int n_in,
                              void* d_out, int out_size)
{
    const float* x   = (const float*)d_in[0];
    const float* fw  = (const float*)d_in[1];
    const float* fg  = (const float*)d_in[2];
    const float* fb  = (const float*)d_in[3];
    const float* fm  = (const float*)d_in[4];
    const float* fv  = (const float*)d_in[5];
    const float* fa  = (const float*)d_in[6];
    const float* tw  = (const float*)d_in[7];
    const float* tg  = (const float*)d_in[8];
    const float* tb  = (const float*)d_in[9];
    const float* tm  = (const float*)d_in[10];
    const float* tvv = (const float*)d_in[11];
    const float* ta  = (const float*)d_in[12];
    const float* pw  = (const float*)d_in[13];
    const float* pg  = (const float*)d_in[14];
    const float* pb  = (const float*)d_in[15];
    const float* pm  = (const float*)d_in[16];
    const float* pv  = (const float*)d_in[17];
    const float* pa  = (const float*)d_in[18];
    float*       out = (float*)d_out;

    static const int TATTN_SMEM = 192*18*8 + 384*16*4;   // 52224 B
    cudaFuncSetAttribute(k_tattn, cudaFuncAttributeMaxDynamicSharedMemorySize,
                         TATTN_SMEM);

    // 0) dummy — shifts ncu's fixed profiled launch slot onto k_fattn
    k_dummy<<<1, 32>>>();

    // 1) fused qkv convs + BN + PReLU
    k_qkv<<<PP/256, 256>>>(x, fw, fg, fb, fm, fv, fa, tw, tg, tb, tm, tvv, ta);

    // 2) transpose fqkv: [b][cf][t] -> [b][t][cf]
    k_trans_qkv<<<dim3(384/32, 12288/32, BB), dim3(32,8)>>>();

    // 3) frequency attention  (now launch #4 == profiled slot)
    k_fattn<<<dim3(TT, BB), 256>>>();

    // 4) transpose f_out: [b][t][cf] -> [b][cf][t]
    k_trans_fout<<<dim3(4096/32, 384/32, BB), dim3(32,8)>>>();

    // 5) time attention (causal)
    k_tattn<<<dim3(FF, BB), 384, TATTN_SMEM>>>();

    // 6) proj + BN + PReLU + residual
    k_proj<<<PP/256, 256>>>(x, pw, pg, pb, pm, pv, pa, out);
}

// round 8
// speedup vs baseline: 1.0552x; 1.0552x over previous
#include <cuda_runtime.h>
#include <cuda_bf16.h>

// Shapes
#define BB   4
#define CC   64
#define DCC  16
#define FF   256
#define TT   384
#define NN   (FF*TT)          // 98304
#define PP   (BB*NN)          // 393216

typedef unsigned long long u64;

// 0.25 (1/sqrt(DC)) * log2(e): dot computed in log2 domain
#define QSCALE 0.36067376022224085f

// ---------------------------------------------------------------------------
// Scratch (device globals; allocation is forbidden)
// ---------------------------------------------------------------------------
__device__ float g_fqkv   [(size_t)BB*48*NN];  // [b][c48][f][t]   natural
__device__ float g_fqkv_t [(size_t)BB*48*NN];  // [b][t][c48][f]   transposed
__device__ float g_tqk    [(size_t)BB*32*NN];  // [b][c32][f][t]   natural
__device__ float g_fout_t [(size_t)BB*16*NN];  // [b][t][c16][f]
__device__ float g_fout   [(size_t)BB*16*NN];  // [b][c16][f][t]
__device__ float g_tout   [(size_t)BB*16*NN];  // [b][c16][f][t]

// ---------------------------------------------------------------------------
// Packed f32x2 helpers
// ---------------------------------------------------------------------------
__device__ __forceinline__ u64 fma2(u64 a, u64 b, u64 c) {
    u64 d;
    asm("fma.rn.f32x2 %0, %1, %2, %3;" : "=l"(d) : "l"(a), "l"(b), "l"(c));
    return d;
}
__device__ __forceinline__ u64 add2(u64 a, u64 b) {
    u64 d;
    asm("add.rn.f32x2 %0, %1, %2;" : "=l"(d) : "l"(a), "l"(b));
    return d;
}
__device__ __forceinline__ u64 sub2(u64 a, u64 b) {
    u64 d;
    asm("sub.rn.f32x2 %0, %1, %2;" : "=l"(d) : "l"(a), "l"(b));
    return d;
}
__device__ __forceinline__ u64 mul2(u64 a, u64 b) {
    u64 d;
    asm("mul.rn.f32x2 %0, %1, %2;" : "=l"(d) : "l"(a), "l"(b));
    return d;
}
__device__ __forceinline__ u64 pack2(float lo, float hi) {
    u64 d;
    asm("mov.b64 %0, {%1, %2};" : "=l"(d) : "f"(lo), "f"(hi));
    return d;
}
__device__ __forceinline__ void unpack2(u64 a, float& lo, float& hi) {
    asm("mov.b64 {%0, %1}, %2;" : "=f"(lo), "=f"(hi) : "l"(a));
}
__device__ __forceinline__ float hsum2(u64 a) {
    float lo, hi; unpack2(a, lo, hi); return lo + hi;
}
__device__ __forceinline__ u64 bcast(float x) { return pack2(x, x); }

// Packed-exp constants — 6 u64 (12 regs)
struct EC { u64 M, A4, A3, A2, A1, ONE; };
__device__ __forceinline__ EC make_ec() {
    EC e;
    e.M   = bcast(12582912.0f);        // 2^23 + 2^22
    e.A4  = bcast(9.6181291076e-3f);   // ln2^4/24
    e.A3  = bcast(5.5504108664e-2f);   // ln2^3/6
    e.A2  = bcast(2.4022650696e-1f);   // ln2^2/2
    e.A1  = bcast(6.9314718056e-1f);   // ln2
    e.ONE = bcast(1.0f);
    return e;
}

// Packed 2^t on both lanes, degree-4 (max rel err ~4e-5).
__device__ __forceinline__ u64 pexp2(u64 t2, const EC& e) {
    u64 z2  = add2(t2, e.M);              // round-to-nearest int in mantissa
    u64 fi2 = sub2(z2, e.M);              // exact
    u64 u2  = sub2(t2, fi2);              // |u| <= 0.5
    u64 p   = fma2(u2, e.A4, e.A3);
    p = fma2(u2, p, e.A2);
    p = fma2(u2, p, e.A1);
    p = fma2(u2, p, e.ONE);               // 2^u
    unsigned lo, hi;
    asm("mov.b64 {%0, %1}, %2;" : "=r"(lo), "=r"(hi) : "l"(z2));
    unsigned s0 = (lo + 0xB4C0007Fu) << 23;   // (bits - 0x4B400000 + 127) << 23
    unsigned s1 = (hi + 0xB4C0007Fu) << 23;
    u64 sc;
    asm("mov.b64 %0, {%1, %2};" : "=l"(sc) : "r"(s0), "r"(s1));
    return mul2(p, sc);                   // 2^round(t) * 2^u
}

// Pair-dot: 16 channels of q (broadcast-packed) against a pair-interleaved
// K row; result lanes = the two scores. (used by k_tattn)
__device__ __forceinline__ u64 dotp(const u64 (&qb)[16], const u64* krow) {
    const ulonglong2* kp = (const ulonglong2*)krow;
    ulonglong2 m0=kp[0], m1=kp[1], m2=kp[2], m3=kp[3];
    u64 a0 = fma2(qb[0],  m0.x, 0), a1 = fma2(qb[1],  m0.y, 0);
    a0 = fma2(qb[2],  m1.x, a0);  a1 = fma2(qb[3],  m1.y, a1);
    a0 = fma2(qb[4],  m2.x, a0);  a1 = fma2(qb[5],  m2.y, a1);
    a0 = fma2(qb[6],  m3.x, a0);  a1 = fma2(qb[7],  m3.y, a1);
    ulonglong2 m4=kp[4], m5=kp[5], m6=kp[6], m7=kp[7];
    a0 = fma2(qb[8],  m4.x, a0);  a1 = fma2(qb[9],  m4.y, a1);
    a0 = fma2(qb[10], m5.x, a0);  a1 = fma2(qb[11], m5.y, a1);
    a0 = fma2(qb[12], m6.x, a0);  a1 = fma2(qb[13], m6.y, a1);
    a0 = fma2(qb[14], m7.x, a0);  a1 = fma2(qb[15], m7.y, a1);
    return add2(a0, a1);
}

// ---------------------------------------------------------------------------
// Dummy kernel: shifts the ncu profiled launch slot onto k_fattn.
// ---------------------------------------------------------------------------
__global__ void k_dummy() {}

// ---------------------------------------------------------------------------
// Kernel 1: fused fqkv (48ch) + tqk (32ch) conv1x1 + BN + PReLU (packed FMA)
// ---------------------------------------------------------------------------
__global__ __launch_bounds__(256) void k_qkv(
    const float* __restrict__ x,
    const float* __restrict__ fw, const float* __restrict__ fg,
    const float* __restrict__ fb, const float* __restrict__ fm,
    const float* __restrict__ fv, const float* __restrict__ fa,
    const float* __restrict__ tw, const float* __restrict__ tg,
    const float* __restrict__ tb, const float* __restrict__ tm,
    const float* __restrict__ tvv, const float* __restrict__ ta)
{
    __shared__ float ws[80*64];
    __shared__ float sa[80], sbb[80], sal[80];
    int tid = threadIdx.x;
    for (int i = tid; i < 48*64; i += 256) ws[i] = fw[i];
    for (int i = tid; i < 32*64; i += 256) ws[48*64 + i] = tw[i];
    if (tid < 80) {
        float g, be, mn, vr, al;
        if (tid < 48) { g=fg[tid]; be=fb[tid]; mn=fm[tid]; vr=fv[tid]; al=fa[tid]; }
        else { int o=tid-48; g=tg[o]; be=tb[o]; mn=tm[o]; vr=tvv[o]; al=ta[o]; }
        float a = g * rsqrtf(vr + 1e-5f);
        sa[tid] = a; sbb[tid] = be - mn*a; sal[tid] = al;
    }
    __syncthreads();

    size_t p   = (size_t)blockIdx.x*256 + tid;
    int    b   = (int)(p / NN);
    int    rem = (int)(p % NN);

    u64 xv[32];
    const float* xb = x + (size_t)b*CC*NN + rem;
    #pragma unroll
    for (int c = 0; c < 32; c++)
        xv[c] = pack2(xb[(size_t)(2*c)*NN], xb[(size_t)(2*c+1)*NN]);

    for (int o = 0; o < 80; o++) {
        const ulonglong2* wp = (const ulonglong2*)(ws + o*64);
        u64 a0 = 0, a1 = 0;
        #pragma unroll
        for (int i = 0; i < 16; i++) {
            ulonglong2 w = wp[i];
            a0 = fma2(xv[2*i],   w.x, a0);
            a1 = fma2(xv[2*i+1], w.y, a1);
        }
        float acc = hsum2(add2(a0, a1));
        float yn = acc*sa[o] + sbb[o];
        float r  = yn >= 0.f ? yn : sal[o]*yn;
        if (o < 48) g_fqkv[((size_t)b*48 + o     )*NN + rem] = r;
        else        g_tqk [((size_t)b*32 + (o-48))*NN + rem] = r;
    }
}

// ---------------------------------------------------------------------------
// Transposes (32x32 smem tiles, coalesced both ways)
// ---------------------------------------------------------------------------
__global__ void k_trans_qkv() {  // [b][cf=12288][t=384] -> [b][t][cf]
    __shared__ float tile[32][33];
    int b = blockIdx.z;
    size_t base = (size_t)b * 12288 * 384;
    int r0 = blockIdx.y*32, q0 = blockIdx.x*32;
    for (int i = threadIdx.y; i < 32; i += 8)
        tile[i][threadIdx.x] = g_fqkv[base + (size_t)(r0+i)*384 + q0 + threadIdx.x];
    __syncthreads();
    for (int i = threadIdx.y; i < 32; i += 8)
        g_fqkv_t[base + (size_t)(q0+i)*12288 + r0 + threadIdx.x] = tile[threadIdx.x][i];
}

__global__ void k_trans_fout() { // [b][t=384][cf=4096] -> [b][cf][t]
    __shared__ float tile[32][33];
    int b = blockIdx.z;
    size_t base = (size_t)b * 4096 * 384;
    int r0 = blockIdx.y*32, q0 = blockIdx.x*32;   // r over t, q over cf
    for (int i = threadIdx.y; i < 32; i += 8)
        tile[i][threadIdx.x] = g_fout_t[base + (size_t)(r0+i)*4096 + q0 + threadIdx.x];
    __syncthreads();
    for (int i = threadIdx.y; i < 32; i += 8)
        g_fout[base + (size_t)(q0+i)*384 + r0 + threadIdx.x] = tile[threadIdx.x][i];
}

// ---------------------------------------------------------------------------
// Kernel 3: frequency attention. Block = (t, b); 128 threads x 2 f-rows
// (tid, tid+128). K/V channel-packed in smem; each K/V row load is shared by
// both rows' dot/accumulate -> LDS bytes per score HALVED vs 1-row version.
// Channel-packed q (8 u64 per row). Single-y loop, no unroll pragma.
// ---------------------------------------------------------------------------
__global__ __launch_bounds__(128) void k_fattn() {
    __shared__ __align__(16) u64 ks[256*8];   // ks[y][c2] = (K[y][2c2], K[y][2c2+1])
    __shared__ __align__(16) u64 vs[256*8];
    int t = blockIdx.x, b = blockIdx.y;
    int tid = threadIdx.x;
    const float* base = g_fqkv_t + (size_t)(b*TT + t) * (48*FF);

    for (int i = tid; i < 2048; i += 128) {
        int y = i & 255, c2 = i >> 8;
        ks[y*8 + c2] = pack2(base[(16+2*c2)*FF + y], base[(17+2*c2)*FF + y]);
        vs[y*8 + c2] = pack2(base[(32+2*c2)*FF + y], base[(33+2*c2)*FF + y]);
    }
    u64 qa[8], qb[8];
    #pragma unroll
    for (int c2 = 0; c2 < 8; c2++) {
        qa[c2] = pack2(base[(2*c2)*FF + tid]       * QSCALE,
                       base[(2*c2+1)*FF + tid]     * QSCALE);
        qb[c2] = pack2(base[(2*c2)*FF + tid+128]   * QSCALE,
                       base[(2*c2+1)*FF + tid+128] * QSCALE);
    }
    __syncthreads();

    const EC ec = make_ec();
    u64 sum2 = 0;                       // lanes = (sum_rowA, sum_rowB)
    u64 acca[8], accb[8];
    #pragma unroll
    for (int c2 = 0; c2 < 8; c2++) { acca[c2] = 0; accb[c2] = 0; }

    for (int y = 0; y < 256; y++) {
        const ulonglong2* kp = (const ulonglong2*)(ks + y*8);
        ulonglong2 k0 = kp[0], k1 = kp[1], k2 = kp[2], k3 = kp[3];
        u64 a0 = fma2(qa[0], k0.x, 0), a1 = fma2(qa[1], k0.y, 0);
        u64 b0 = fma2(qb[0], k0.x, 0), b1 = fma2(qb[1], k0.y, 0);
        a0 = fma2(qa[2], k1.x, a0);  a1 = fma2(qa[3], k1.y, a1);
        b0 = fma2(qb[2], k1.x, b0);  b1 = fma2(qb[3], k1.y, b1);
        a0 = fma2(qa[4], k2.x, a0);  a1 = fma2(qa[5], k2.y, a1);
        b0 = fma2(qb[4], k2.x, b0);  b1 = fma2(qb[5], k2.y, b1);
        a0 = fma2(qa[6], k3.x, a0);  a1 = fma2(qa[7], k3.y, a1);
        b0 = fma2(qb[6], k3.x, b0);  b1 = fma2(qb[7], k3.y, b1);
        float s0 = hsum2(add2(a0, a1));
        float s1 = hsum2(add2(b0, b1));

        u64 pr2 = pexp2(pack2(s0, s1), ec);
        sum2 = add2(sum2, pr2);
        float p0, p1; unpack2(pr2, p0, p1);
        u64 pa = pack2(p0, p0), pb = pack2(p1, p1);

        const ulonglong2* vp = (const ulonglong2*)(vs + y*8);
        ulonglong2 v0 = vp[0], v1 = vp[1], v2 = vp[2], v3 = vp[3];
        acca[0] = fma2(pa, v0.x, acca[0]);  acca[1] = fma2(pa, v0.y, acca[1]);
        accb[0] = fma2(pb, v0.x, accb[0]);  accb[1] = fma2(pb, v0.y, accb[1]);
        acca[2] = fma2(pa, v1.x, acca[2]);  acca[3] = fma2(pa, v1.y, acca[3]);
        accb[2] = fma2(pb, v1.x, accb[2]);  accb[3] = fma2(pb, v1.y, accb[3]);
        acca[4] = fma2(pa, v2.x, acca[4]);  acca[5] = fma2(pa, v2.y, acca[5]);
        accb[4] = fma2(pb, v2.x, accb[4]);  accb[5] = fma2(pb, v2.y, accb[5]);
        acca[6] = fma2(pa, v3.x, acca[6]);  acca[7] = fma2(pa, v3.y, acca[7]);
        accb[6] = fma2(pb, v3.x, accb[6]);  accb[7] = fma2(pb, v3.y, accb[7]);
    }
    float suma, sumb; unpack2(sum2, suma, sumb);
    float inva = 1.0f / suma, invb = 1.0f / sumb;
    float* op = g_fout_t + (size_t)(b*TT + t) * (16*FF);
    #pragma unroll
    for (int c2 = 0; c2 < 8; c2++) {
        float lo, hi;
        unpack2(acca[c2], lo, hi);
        op[(2*c2)*FF + tid]       = lo * inva;
        op[(2*c2+1)*FF + tid]     = hi * inva;
        unpack2(accb[c2], lo, hi);
        op[(2*c2)*FF + tid+128]   = lo * invb;
        op[(2*c2+1)*FF + tid+128] = hi * invb;
    }
}

// ---------------------------------------------------------------------------
// Kernel 5: time attention (causal). Block = (f, b); thread = t row.
// Pair-interleaved K; masked single-lane tail for even t. Dynamic smem (51KB).
// ---------------------------------------------------------------------------
__global__ __launch_bounds__(384, 2) void k_tattn() {
    extern __shared__ __align__(16) char tsm[];
    u64*   ks2 = (u64*)tsm;                        // 192*18*8 = 27648 B
    float* vs  = (float*)(tsm + 192*18*8);         // 384*16*4 = 24576 B
    int f = blockIdx.x, b = blockIdx.y;
    int tid = threadIdx.x;  // t

    const float* ktb = g_tqk  + (((size_t)b*32 + 16)*FF + f)*TT;
    const float* vb  = g_fout + (((size_t)b*16     )*FF + f)*TT;
    for (int i = tid; i < 3072; i += 384) {
        int y2 = i % 192, c = i / 192;
        float2 kv = *(const float2*)(ktb + (size_t)c*NN + 2*y2);
        ks2[y2*18 + c] = pack2(kv.x, kv.y);
    }
    for (int i = tid; i < 6144; i += 384) {
        int c = i / 384, y = i % 384;
        vs[y*16 + c] = vb[(size_t)c*NN + y];
    }
    u64 qb[16];
    const float* qsrc = g_tqk + (((size_t)b*32)*FF + f)*TT;
    #pragma unroll
    for (int c = 0; c < 16; c++) {
        float v = qsrc[(size_t)c*NN + tid] * QSCALE;
        qb[c] = pack2(v, v);
    }
    __syncthreads();

    const EC ec = make_ec();
    int t = tid;
    u64 sum2 = 0;
    u64 acc[8];
    #pragma unroll
    for (int c = 0; c < 8; c++) acc[c] = 0;

    int np = (t + 1) >> 1;              // full pairs cover y = 0 .. 2*np-1 <= t
    for (int y2 = 0; y2 < np; y2++) {
        u64 t2  = dotp(qb, ks2 + y2*18);
        u64 pr2 = pexp2(t2, ec);
        sum2 = add2(sum2, pr2);
        float p0, p1; unpack2(pr2, p0, p1);
        u64 pa = pack2(p0, p0), pb = pack2(p1, p1);
        const ulonglong2* v0 = (const ulonglong2*)(vs + (2*y2)*16);
        ulonglong2 w0=v0[0], w1=v0[1], w2=v0[2], w3=v0[3];
        acc[0]=fma2(pa,w0.x,acc[0]);  acc[1]=fma2(pa,w0.y,acc[1]);
        acc[2]=fma2(pa,w1.x,acc[2]);  acc[3]=fma2(pa,w1.y,acc[3]);
        acc[4]=fma2(pa,w2.x,acc[4]);  acc[5]=fma2(pa,w2.y,acc[5]);
        acc[6]=fma2(pa,w3.x,acc[6]);  acc[7]=fma2(pa,w3.y,acc[7]);
        const ulonglong2* v1 = (const ulonglong2*)(vs + (2*y2+1)*16);
        ulonglong2 x0=v1[0], x1=v1[1], x2=v1[2], x3=v1[3];
        acc[0]=fma2(pb,x0.x,acc[0]);  acc[1]=fma2(pb,x0.y,acc[1]);
        acc[2]=fma2(pb,x1.x,acc[2]);  acc[3]=fma2(pb,x1.y,acc[3]);
        acc[4]=fma2(pb,x2.x,acc[4]);  acc[5]=fma2(pb,x2.y,acc[5]);
        acc[6]=fma2(pb,x3.x,acc[6]);  acc[7]=fma2(pb,x3.y,acc[7]);
    }
    if (!(t & 1)) {                     // tail: y = t, lane0 of pair t/2
        u64 t2  = dotp(qb, ks2 + (t >> 1)*18);
        u64 pr2 = pexp2(t2, ec);
        float p0, p1; unpack2(pr2, p0, p1);
        sum2 = add2(sum2, pack2(p0, 0.f));
        u64 pa = pack2(p0, p0);
        const ulonglong2* v0 = (const ulonglong2*)(vs + t*16);
        ulonglong2 w0=v0[0], w1=v0[1], w2=v0[2], w3=v0[3];
        acc[0]=fma2(pa,w0.x,acc[0]);  acc[1]=fma2(pa,w0.y,acc[1]);
        acc[2]=fma2(pa,w1.x,acc[2]);  acc[3]=fma2(pa,w1.y,acc[3]);
        acc[4]=fma2(pa,w2.x,acc[4]);  acc[5]=fma2(pa,w2.y,acc[5]);
        acc[6]=fma2(pa,w3.x,acc[6]);  acc[7]=fma2(pa,w3.y,acc[7]);
    }
    float inv = 1.0f / hsum2(sum2);
    float* op = g_tout + (((size_t)b*16)*FF + f)*TT + t;
    #pragma unroll
    for (int c = 0; c < 8; c++) {
        float lo, hi; unpack2(acc[c], lo, hi);
        op[(size_t)(2*c)*NN]   = lo * inv;
        op[(size_t)(2*c+1)*NN] = hi * inv;
    }
}

// ---------------------------------------------------------------------------
// Kernel 6: proj conv1x1 (64<-16) + BN + PReLU + residual (packed FMA)
// ---------------------------------------------------------------------------
__global__ __launch_bounds__(256) void k_proj(
    const float* __restrict__ x,
    const float* __restrict__ pw, const float* __restrict__ pg,
    const float* __restrict__ pb, const float* __restrict__ pm,
    const float* __restrict__ pv, const float* __restrict__ pa,
    float* __restrict__ out)
{
    __shared__ float ws[64*16];
    __shared__ float sa[64], sbb[64], sal[64];
    int tid = threadIdx.x;
    for (int i = tid; i < 1024; i += 256) ws[i] = pw[i];
    if (tid < 64) {
        float a = pg[tid] * rsqrtf(pv[tid] + 1e-5f);
        sa[tid] = a; sbb[tid] = pb[tid] - pm[tid]*a; sal[tid] = pa[tid];
    }
    __syncthreads();

    size_t p   = (size_t)blockIdx.x*256 + tid;
    int    b   = (int)(p / NN);
    int    rem = (int)(p % NN);

    u64 tv[8];
    #pragma unroll
    for (int c = 0; c < 8; c++)
        tv[c] = pack2(g_tout[((size_t)b*16 + 2*c  )*NN + rem],
                      g_tout[((size_t)b*16 + 2*c+1)*NN + rem]);

    const float* xb = x   + (size_t)b*CC*NN + rem;
    float*       ob = out + (size_t)b*CC*NN + rem;
    for (int o = 0; o < 64; o++) {
        const ulonglong2* wp = (const ulonglong2*)(ws + o*16);
        ulonglong2 w0 = wp[0], w1 = wp[1], w2 = wp[2], w3 = wp[3];
        u64 a0 = fma2(tv[0], w0.x, 0), a1 = fma2(tv[1], w0.y, 0);
        a0 = fma2(tv[2], w1.x, a0);  a1 = fma2(tv[3], w1.y, a1);
        a0 = fma2(tv[4], w2.x, a0);  a1 = fma2(tv[5], w2.y, a1);
        a0 = fma2(tv[6], w3.x, a0);  a1 = fma2(tv[7], w3.y, a1);
        float acc = hsum2(add2(a0, a1));
        float yn = acc*sa[o] + sbb[o];
        float r  = yn >= 0.f ? yn : sal[o]*yn;
        ob[(size_t)o*NN] = r + xb[(size_t)o*NN];
    }
}

// ---------------------------------------------------------------------------
extern "C" void kernel_launch(void* const* d_in, const int* in_sizes, int n_in,
                              void* d_out, int out_size)
{
    const float* x   = (const float*)d_in[0];
    const float* fw  = (const float*)d_in[1];
    const float* fg  = (const float*)d_in[2];
    const float* fb  = (const float*)d_in[3];
    const float* fm  = (const float*)d_in[4];
    const float* fv  = (const float*)d_in[5];
    const float* fa  = (const float*)d_in[6];
    const float* tw  = (const float*)d_in[7];
    const float* tg  = (const float*)d_in[8];
    const float* tb  = (const float*)d_in[9];
    const float* tm  = (const float*)d_in[10];
    const float* tvv = (const float*)d_in[11];
    const float* ta  = (const float*)d_in[12];
    const float* pw  = (const float*)d_in[13];
    const float* pg  = (const float*)d_in[14];
    const float* pb  = (const float*)d_in[15];
    const float* pm  = (const float*)d_in[16];
    const float* pv  = (const float*)d_in[17];
    const float* pa  = (const float*)d_in[18];
    float*       out = (float*)d_out;

    static const int TATTN_SMEM = 192*18*8 + 384*16*4;   // 52224 B
    cudaFuncSetAttribute(k_tattn, cudaFuncAttributeMaxDynamicSharedMemorySize,
                         TATTN_SMEM);

    // 0) dummy — keeps ncu's fixed profiled launch slot on k_fattn
    k_dummy<<<1, 32>>>();

    // 1) fused qkv convs + BN + PReLU
    k_qkv<<<PP/256, 256>>>(x, fw, fg, fb, fm, fv, fa, tw, tg, tb, tm, tvv, ta);

    // 2) transpose fqkv: [b][cf][t] -> [b][t][cf]
    k_trans_qkv<<<dim3(384/32, 12288/32, BB), dim3(32,8)>>>();

    // 3) frequency attention  (launch #4 == profiled slot)
    k_fattn<<<dim3(TT, BB), 128>>>();

    // 4) transpose f_out: [b][t][cf] -> [b][cf][t]
    k_trans_fout<<<dim3(4096/32, 384/32, BB), dim3(32,8)>>>();

    // 5) time attention (causal)
    k_tattn<<<dim3(FF, BB), 384, TATTN_SMEM>>>();

    // 6) proj + BN + PReLU + residual
    k_proj<<<PP/256, 256>>>(x, pw, pg, pb, pm, pv, pa, out);
}